// round 2
// baseline (speedup 1.0000x reference)
#include <cuda_runtime.h>
#include <math.h>

#define HW   (128*128)       // 16384
#define CHW  (16*HW)         // 262144 floats per slice-set entry (16 channels)

// ---------------- scratch ----------------
__device__ float g_s1[9*CHW];     // ping
__device__ float g_s2[9*CHW];     // pong
__device__ float g_skip[5*CHW];   // resblock-A output (skip for resblock B)
__device__ float g_mean[16];
__device__ float g_istd[16];

struct TapMap  { int   m[9][3]; };
struct MultArr { float m[9];    };
struct SkipMap { int   m[9];    };

// ---------------- generic 2D conv stage ----------------
// For output slice `osl`, accumulate over kx taps: tap kx uses input slice
// tm.m[osl][kx] (or -1 = zero pad) with weights w[:,:,:,:,kx] as a 3x3 2D conv.
__global__ __launch_bounds__(256) void conv_stage(
    const float* __restrict__ in, float* __restrict__ out,
    const float* __restrict__ w, const float* __restrict__ bias, TapMap tm)
{
    __shared__ float s_w[16*9*16];      // [ci][k9][co]
    __shared__ float s_in[16*18*18];    // [ci][r][c]

    const int osl  = blockIdx.y;
    const int tile = blockIdx.x;
    const int tz0 = (tile >> 3) << 4;
    const int ty0 = (tile &  7) << 4;
    const int tid = threadIdx.x;
    const int tz = tid >> 4, ty = tid & 15;

    float acc[16];
#pragma unroll
    for (int i = 0; i < 16; i++) acc[i] = 0.f;

    for (int kx = 0; kx < 3; kx++) {
        const int isl = tm.m[osl][kx];
        if (isl < 0) continue;
        __syncthreads();
        // weights for this tap: w layout [co][ci][kz][ky][kx]
        for (int idx = tid; idx < 2304; idx += 256) {
            int co = idx & 15;
            int k  = (idx >> 4) % 9;
            int ci = idx / 144;
            s_w[idx] = w[((co*16 + ci)*9 + k)*3 + kx];
        }
        // input tile with halo
        const float* ip = in + (size_t)isl * CHW;
        for (int idx = tid; idx < 16*18*18; idx += 256) {
            int c  = idx % 18;
            int r  = (idx / 18) % 18;
            int ci = idx / 324;
            int gz = tz0 + r - 1, gy = ty0 + c - 1;
            float v = 0.f;
            if ((unsigned)gz < 128u && (unsigned)gy < 128u)
                v = ip[ci*HW + gz*128 + gy];
            s_in[idx] = v;
        }
        __syncthreads();

#pragma unroll
        for (int ci = 0; ci < 16; ci++) {
            float v[9];
#pragma unroll
            for (int kz = 0; kz < 3; kz++)
#pragma unroll
                for (int ky = 0; ky < 3; ky++)
                    v[kz*3+ky] = s_in[ci*324 + (tz+kz)*18 + (ty+ky)];
#pragma unroll
            for (int k = 0; k < 9; k++) {
                const float4* wp = reinterpret_cast<const float4*>(&s_w[(ci*9 + k)*16]);
                float4 w0 = wp[0], w1 = wp[1], w2 = wp[2], w3 = wp[3];
                float vv = v[k];
                acc[0]  += w0.x*vv; acc[1]  += w0.y*vv; acc[2]  += w0.z*vv; acc[3]  += w0.w*vv;
                acc[4]  += w1.x*vv; acc[5]  += w1.y*vv; acc[6]  += w1.z*vv; acc[7]  += w1.w*vv;
                acc[8]  += w2.x*vv; acc[9]  += w2.y*vv; acc[10] += w2.z*vv; acc[11] += w2.w*vv;
                acc[12] += w3.x*vv; acc[13] += w3.y*vv; acc[14] += w3.z*vv; acc[15] += w3.w*vv;
            }
        }
    }

    const int oz = tz0 + tz, oy = ty0 + ty;
    float* op = out + (size_t)osl*CHW + oz*128 + oy;
#pragma unroll
    for (int co = 0; co < 16; co++)
        op[co*HW] = acc[co] + bias[co];
}

// ---------------- instance-norm statistics ----------------
// One block per channel; multiplicity-weighted mean/var over all 128^3 voxels.
__global__ __launch_bounds__(256) void in_stats(
    const float* __restrict__ buf, int n_slices, MultArr ma)
{
    __shared__ double sh_s[256], sh_q[256];
    const int c = blockIdx.x, tid = threadIdx.x;
    double s = 0.0, q = 0.0;
    for (int sl = 0; sl < n_slices; sl++) {
        const float* p = buf + (size_t)(sl*16 + c)*HW;
        float ls = 0.f, lq = 0.f;
        for (int i = tid; i < HW; i += 256) { float v = p[i]; ls += v; lq += v*v; }
        double m = (double)ma.m[sl];
        s += m * (double)ls;
        q += m * (double)lq;
    }
    sh_s[tid] = s; sh_q[tid] = q; __syncthreads();
    for (int o = 128; o > 0; o >>= 1) {
        if (tid < o) { sh_s[tid] += sh_s[tid+o]; sh_q[tid] += sh_q[tid+o]; }
        __syncthreads();
    }
    if (tid == 0) {
        double mean = sh_s[0] / 2097152.0;
        double var  = sh_q[0] / 2097152.0 - mean*mean;
        g_mean[c] = (float)mean;
        g_istd[c] = (float)(1.0 / sqrt(var + 1e-5));
    }
}

// ---------------- normalize (+skip) + relu ----------------
__global__ __launch_bounds__(256) void norm_relu(float* buf, int total)
{
    int i = blockIdx.x*256 + threadIdx.x;
    if (i >= total) return;
    int c = (i >> 14) & 15;
    float v = (buf[i] - g_mean[c]) * g_istd[c];
    buf[i] = fmaxf(v, 0.f);
}

__global__ __launch_bounds__(256) void norm_skip_relu(
    const float* __restrict__ buf, float* __restrict__ outb,
    const float* __restrict__ skip, int total)
{
    int i = blockIdx.x*256 + threadIdx.x;
    if (i >= total) return;
    int c   = (i >> 14) & 15;
    int pix = i & (HW - 1);
    float v = (buf[i] - g_mean[c]) * g_istd[c] + skip[c*HW + pix];
    outb[i] = fmaxf(v, 0.f);
}

__global__ __launch_bounds__(256) void norm_skipmap_relu(
    float* buf, const float* __restrict__ skip, SkipMap sm, int total)
{
    int i = blockIdx.x*256 + threadIdx.x;
    if (i >= total) return;
    int sl  = i >> 18;          // CHW = 2^18
    int c   = (i >> 14) & 15;
    int pix = i & (HW - 1);
    float v = (buf[i] - g_mean[c]) * g_istd[c]
            + skip[(size_t)(sm.m[sl]*16 + c)*HW + pix];
    buf[i] = fmaxf(v, 0.f);
}

// ---------------- fused forward projection ----------------
// out[c,0,z,u] = sum_x vol = weighted slice sum at (c,z,y=u)
// out[c,1,z,u] = sum_y of the slice selected by x=u
//   EXCEPT u==0: reference fp32 rounding makes x=+-3.9e-15 at uu=0, so the
//   valid mask kills tt<=63 (i.e. y in [64,127]) -> only y=0..63 contribute.
__global__ __launch_bounds__(128) void forward_proj(
    const float* __restrict__ F, float* __restrict__ out)
{
    __shared__ float red[9][4];
    __shared__ float rs[9];
    const int cz = blockIdx.x;
    const int c = cz >> 7, z = cz & 127;
    const int u = threadIdx.x;
    const float mult[9] = {1.f,1.f,1.f,1.f,120.f,1.f,1.f,1.f,1.f};

    const int base = c*HW + z*128 + u;
    float vals[9];
    float s0 = 0.f;
#pragma unroll
    for (int s = 0; s < 9; s++) {
        vals[s] = F[(size_t)s*CHW + base];
        s0 += mult[s] * vals[s];
    }
    out[(c*2 + 0)*HW + z*128 + u] = s0;

    const int lane = u & 31, wid = u >> 5;
#pragma unroll
    for (int s = 0; s < 9; s++) {
        float v = vals[s];
#pragma unroll
        for (int o = 16; o > 0; o >>= 1) v += __shfl_xor_sync(0xffffffffu, v, o);
        if (lane == 0) red[s][wid] = v;
    }
    __syncthreads();
    if (u < 9) rs[u] = red[u][0] + red[u][1] + red[u][2] + red[u][3];
    __syncthreads();
    const int sl = (u < 4) ? u : (u > 123 ? u - 119 : 4);
    float o1;
    if (u == 0) {
        // half column sum of slice 0: y = 0..63 (warps 0 and 1)
        o1 = red[0][0] + red[0][1];
    } else {
        o1 = rs[sl];
    }
    out[(c*2 + 1)*HW + z*128 + u] = o1;
}

// ---------------- launch ----------------
extern "C" void kernel_launch(void* const* d_in, const int* in_sizes, int n_in,
                              void* d_out, int out_size)
{
    (void)in_sizes; (void)n_in; (void)out_size;
    const float* V    = (const float*)d_in[0];   // (1,16,1,128,128) == [c][z][y]
    const float* w_a1 = (const float*)d_in[1];
    const float* b_a1 = (const float*)d_in[2];
    const float* w_a2 = (const float*)d_in[3];
    const float* b_a2 = (const float*)d_in[4];
    const float* w_b1 = (const float*)d_in[5];
    const float* b_b1 = (const float*)d_in[6];
    const float* w_b2 = (const float*)d_in[7];
    const float* b_b2 = (const float*)d_in[8];
    float* out = (float*)d_out;

    float *s1, *s2, *sk;
    cudaGetSymbolAddress((void**)&s1, g_s1);
    cudaGetSymbolAddress((void**)&s2, g_s2);
    cudaGetSymbolAddress((void**)&sk, g_skip);

    // tap maps: m[out_slice][kx] = input slice id (-1 = zero pad)
    TapMap mA1 = {{ {-1,0,0},{0,0,0},{0,0,-1} }};
    TapMap mA2 = {{ {-1,0,1},{0,1,1},{1,1,1},{1,1,2},{1,2,-1} }};
    TapMap mB1 = {{ {-1,0,1},{0,1,2},{1,2,2},{2,2,2},{2,2,3},{2,3,4},{3,4,-1} }};
    TapMap mB2 = {{ {-1,0,1},{0,1,2},{1,2,3},{2,3,3},{3,3,3},{3,3,4},{3,4,5},{4,5,6},{5,6,-1} }};

    MultArr uA1 = {{1.f,126.f,1.f}};
    MultArr uA2 = {{1.f,1.f,124.f,1.f,1.f}};
    MultArr uB1 = {{1.f,1.f,1.f,122.f,1.f,1.f,1.f}};
    MultArr uB2 = {{1.f,1.f,1.f,1.f,120.f,1.f,1.f,1.f,1.f}};

    SkipMap skm = {{0,1,2,2,2,2,2,3,4}};

    // ---- resblock A ----
    conv_stage<<<dim3(64,3), 256>>>(V,  s1, w_a1, b_a1, mA1);
    in_stats  <<<16, 256>>>(s1, 3, uA1);
    norm_relu <<<(3*CHW+255)/256, 256>>>(s1, 3*CHW);

    conv_stage<<<dim3(64,5), 256>>>(s1, s2, w_a2, b_a2, mA2);
    in_stats  <<<16, 256>>>(s2, 5, uA2);
    norm_skip_relu<<<(5*CHW+255)/256, 256>>>(s2, sk, V, 5*CHW);

    // ---- resblock B ----
    conv_stage<<<dim3(64,7), 256>>>(sk, s1, w_b1, b_b1, mB1);
    in_stats  <<<16, 256>>>(s1, 7, uB1);
    norm_relu <<<(7*CHW+255)/256, 256>>>(s1, 7*CHW);

    conv_stage<<<dim3(64,9), 256>>>(s1, s2, w_b2, b_b2, mB2);
    in_stats  <<<16, 256>>>(s2, 9, uB2);
    norm_skipmap_relu<<<(9*CHW+255)/256, 256>>>(s2, sk, skm, 9*CHW);

    // ---- forward projection ----
    forward_proj<<<16*128, 128>>>(s2, out);
}